// round 4
// baseline (speedup 1.0000x reference)
#include <cuda_runtime.h>

// OHLCVPackedScaler: grouped (sample_id, group_id) mean/std over [B,S,D] with
// observed mask. B=4, S=4096, D=32, sid in [0,8), vid in [0,7) -> gid in [0,4).
// 128 groups total -> one CTA per group, no atomics, no scratch.
// Mask dtype is auto-detected (bool bytes / int32 / float32).

namespace {
constexpr int B_ = 4;
constexpr int S_ = 4096;
constexpr int D_ = 32;
constexpr int NSID = 8;
constexpr int GPB = NSID * 4;   // 32 groups per batch
constexpr int NT = 256;
constexpr int NW = NT / 32;
}

// MODE: 0 = bool bytes (1B/elem), 1 = int32 words (4B/elem), 2 = float32 (4B/elem)
template<int MODE>
__device__ __forceinline__ void accum_stats(
    const float* __restrict__ tb, const void* __restrict__ ob,
    const int* __restrict__ sids, const int* __restrict__ vids,
    int sid, int g, float& N, float& SM, float& Q)
{
    float nx=0.f, ny=0.f, nz=0.f, nw=0.f;
    float sx=0.f, sy=0.f, sz=0.f, sw=0.f;
    float qx=0.f, qy=0.f, qz=0.f, qw=0.f;

    for (int s = threadIdx.x; s < S_; s += NT) {
        int v  = __ldg(vids + s);
        int gg = (v < 4) ? 0 : (v - 3);
        if (__ldg(sids + s) == sid && gg == g) {
            const float4* tp = reinterpret_cast<const float4*>(tb + (size_t)s * D_);
            #pragma unroll
            for (int i = 0; i < 8; i++) {
                float4 t = tp[i];
                float wx, wy, wz, ww;
                if (MODE == 0) {
                    unsigned int m = reinterpret_cast<const unsigned int*>(ob)[s * 8 + i];
                    wx = (m & 0x000000FFu) ? 1.f : 0.f;
                    wy = (m & 0x0000FF00u) ? 1.f : 0.f;
                    wz = (m & 0x00FF0000u) ? 1.f : 0.f;
                    ww = (m & 0xFF000000u) ? 1.f : 0.f;
                } else if (MODE == 1) {
                    uint4 m = reinterpret_cast<const uint4*>(ob)[s * 8 + i];
                    wx = m.x ? 1.f : 0.f;
                    wy = m.y ? 1.f : 0.f;
                    wz = m.z ? 1.f : 0.f;
                    ww = m.w ? 1.f : 0.f;
                } else {
                    float4 m = reinterpret_cast<const float4*>(ob)[s * 8 + i];
                    wx = (m.x != 0.f) ? 1.f : 0.f;
                    wy = (m.y != 0.f) ? 1.f : 0.f;
                    wz = (m.z != 0.f) ? 1.f : 0.f;
                    ww = (m.w != 0.f) ? 1.f : 0.f;
                }
                nx += wx;            ny += wy;            nz += wz;            nw += ww;
                sx += wx * t.x;      sy += wy * t.y;      sz += wz * t.z;      sw += ww * t.w;
                qx += wx * t.x*t.x;  qy += wy * t.y*t.y;  qz += wz * t.z*t.z;  qw += ww * t.w*t.w;
            }
        }
    }
    N  = (nx + ny) + (nz + nw);
    SM = (sx + sy) + (sz + sw);
    Q  = (qx + qy) + (qz + qw);
}

__global__ __launch_bounds__(NT) void ohlcv_scaler_kernel(
    const float* __restrict__ target,
    const void* __restrict__ obs,            // dtype auto-detected
    const int* __restrict__ sample_id,
    const int* __restrict__ variate_id,
    float* __restrict__ out)
{
    const int gidx = blockIdx.x;           // 0..127
    const int b    = gidx / GPB;
    const int rem  = gidx - b * GPB;
    const int sid  = rem >> 2;             // 0..7
    const int g    = rem & 3;              // 0..3

    const int*  __restrict__ sids = sample_id  + b * S_;
    const int*  __restrict__ vids = variate_id + b * S_;
    const float* __restrict__ tb  = target + (size_t)b * S_ * D_;

    // ---- mask dtype detection (pure function of input memory) ----
    // float32: a 1.0f word (0x3F800000) > 0x01010101 appears in first 64 words
    //          with overwhelming probability (90% observed rate).
    // bool bytes: words are packings of {0,1} bytes, i.e. <= 0x01010101, and
    //          some word > 1 (multiple/ high-position bytes set).
    // int32: every word is exactly 0 or 1.
    int mode = 1;
    {
        const unsigned int* w = reinterpret_cast<const unsigned int*>(obs);
        #pragma unroll 8
        for (int i = 0; i < 64; i++) {
            unsigned int x = __ldg(w + i);
            if (x > 0x01010101u) { mode = 2; break; }
            if (x > 1u) mode = 0;
        }
    }

    float n, sm, qq;
    const void* ob;
    if (mode == 0)      ob = (const void*)((const unsigned char*)obs + (size_t)b * S_ * D_);
    else                ob = (const void*)((const unsigned char*)obs + (size_t)b * S_ * D_ * 4);

    if (mode == 0)      accum_stats<0>(tb, ob, sids, vids, sid, g, n, sm, qq);
    else if (mode == 1) accum_stats<1>(tb, ob, sids, vids, sid, g, n, sm, qq);
    else                accum_stats<2>(tb, ob, sids, vids, sid, g, n, sm, qq);

    #pragma unroll
    for (int o = 16; o > 0; o >>= 1) {
        n  += __shfl_down_sync(0xFFFFFFFFu, n,  o);
        sm += __shfl_down_sync(0xFFFFFFFFu, sm, o);
        qq += __shfl_down_sync(0xFFFFFFFFu, qq, o);
    }

    __shared__ float rn[NW], rs[NW], rq[NW];
    __shared__ float sh_loc, sh_scale;
    const int lane = threadIdx.x & 31;
    const int warp = threadIdx.x >> 5;
    if (lane == 0) { rn[warp] = n; rs[warp] = sm; rq[warp] = qq; }
    __syncthreads();

    if (threadIdx.x == 0) {
        float N = 0.f, SM = 0.f, Q = 0.f;
        #pragma unroll
        for (int i = 0; i < NW; i++) { N += rn[i]; SM += rs[i]; Q += rq[i]; }

        // uni2ts safe_div semantics: denom==0 -> divide by 1 (numer unchanged)
        float dN  = (N == 0.f) ? 1.f : N;
        float loc = SM / dN;
        // sum((t-loc)^2 * obs) expanded; clamp tiny negative rounding
        float vs  = fmaxf(Q - 2.f * loc * SM + loc * loc * N, 0.f);
        float dC  = N - 1.f;
        if (dC == 0.f) dC = 1.f;
        float var   = vs / dC;
        float scale = sqrtf(var + 1e-5f);
        if (sid == 0) { loc = 0.f; scale = 1.f; }   // padding rows
        sh_loc = loc;
        sh_scale = scale;
    }
    __syncthreads();

    const float loc   = sh_loc;
    const float scale = sh_scale;
    float* __restrict__ out_loc = out + (size_t)b * S_;
    float* __restrict__ out_sc  = out + (size_t)B_ * S_ + (size_t)b * S_;

    for (int s = threadIdx.x; s < S_; s += NT) {
        int v  = vids[s];
        int gg = (v < 4) ? 0 : (v - 3);
        if (sids[s] == sid && gg == g) {
            out_loc[s] = loc;
            out_sc[s]  = scale;
        }
    }
}

extern "C" void kernel_launch(void* const* d_in, const int* in_sizes, int n_in,
                              void* d_out, int out_size) {
    (void)in_sizes; (void)n_in; (void)out_size;
    const float* target     = (const float*)d_in[0];
    const void*  obs        = (const void*)d_in[1];
    const int*   sample_id  = (const int*)d_in[2];
    const int*   variate_id = (const int*)d_in[3];
    float*       out        = (float*)d_out;
    ohlcv_scaler_kernel<<<B_ * GPB, NT>>>(target, obs, sample_id, variate_id, out);
}

// round 5
// speedup vs baseline: 2.0504x; 2.0504x over previous
#include <cuda_runtime.h>

// OHLCVPackedScaler — two-phase grouped mean/std.
// Phase 1: dense coalesced chunk scan -> per-(chunk,group) partial moments.
// Phase 2: fixed-order reduce + loc/scale + output scatter.

namespace {
constexpr int B_ = 4;
constexpr int S_ = 4096;
constexpr int D_ = 32;
constexpr int NG = 32;            // (sid 0..7) x (gid 0..3)
constexpr int NC = 64;            // chunks per batch
constexpr int CHUNK = S_ / NC;    // 64 tokens
constexpr int T1 = 256;           // chunk * 4 quarters
constexpr int T2 = 256;
constexpr int SUB = 8;            // write-blocks per batch in phase 2
}

__device__ float g_part[B_ * NC * NG * 3];   // [b][c][grp][{n,s,q}]

__device__ __forceinline__ int detect_mode(const void* obs) {
    // 0 = bool bytes, 1 = int32 words, 2 = float32
    const unsigned int* w = reinterpret_cast<const unsigned int*>(obs);
    int mode = 1;
    #pragma unroll 8
    for (int i = 0; i < 64; i++) {
        unsigned int x = __ldg(w + i);
        if (x > 0x01010101u) { mode = 2; break; }
        if (x > 1u) mode = 0;
    }
    return mode;
}

__global__ __launch_bounds__(T1) void k1_partials(
    const float* __restrict__ target,
    const void* __restrict__ obs,
    const int* __restrict__ sample_id,
    const int* __restrict__ variate_id)
{
    const int b = blockIdx.x / NC;
    const int c = blockIdx.x - b * NC;
    const int tid = threadIdx.x;
    const int tok_l = tid >> 2;          // 0..63
    const int q     = tid & 3;           // quarter: dims q*8..q*8+7
    const int s     = c * CHUNK + tok_l; // token within batch

    const int mode = detect_mode(obs);

    const int sid = __ldg(sample_id + b * S_ + s);
    const int v   = __ldg(variate_id + b * S_ + s);
    const int grp = sid * 4 + ((v < 4) ? 0 : (v - 3));

    // target quarter: 2x float4
    const float4* tp = reinterpret_cast<const float4*>(
        target + (size_t)(b * S_ + s) * D_) + q * 2;
    float4 t0 = __ldg(tp);
    float4 t1 = __ldg(tp + 1);

    // mask quarter -> 8 weights
    float w[8];
    const size_t eoff = (size_t)(b * S_ + s) * D_ + q * 8;   // element offset
    if (mode == 0) {
        uint2 m = __ldg(reinterpret_cast<const uint2*>((const unsigned char*)obs + eoff));
        w[0] = (m.x & 0x000000FFu) ? 1.f : 0.f;
        w[1] = (m.x & 0x0000FF00u) ? 1.f : 0.f;
        w[2] = (m.x & 0x00FF0000u) ? 1.f : 0.f;
        w[3] = (m.x & 0xFF000000u) ? 1.f : 0.f;
        w[4] = (m.y & 0x000000FFu) ? 1.f : 0.f;
        w[5] = (m.y & 0x0000FF00u) ? 1.f : 0.f;
        w[6] = (m.y & 0x00FF0000u) ? 1.f : 0.f;
        w[7] = (m.y & 0xFF000000u) ? 1.f : 0.f;
    } else if (mode == 1) {
        const uint4* mp = reinterpret_cast<const uint4*>((const unsigned int*)obs + eoff);
        uint4 m0 = __ldg(mp), m1 = __ldg(mp + 1);
        w[0] = m0.x ? 1.f : 0.f;  w[1] = m0.y ? 1.f : 0.f;
        w[2] = m0.z ? 1.f : 0.f;  w[3] = m0.w ? 1.f : 0.f;
        w[4] = m1.x ? 1.f : 0.f;  w[5] = m1.y ? 1.f : 0.f;
        w[6] = m1.z ? 1.f : 0.f;  w[7] = m1.w ? 1.f : 0.f;
    } else {
        const float4* mp = reinterpret_cast<const float4*>((const float*)obs + eoff);
        float4 m0 = __ldg(mp), m1 = __ldg(mp + 1);
        w[0] = (m0.x != 0.f) ? 1.f : 0.f;  w[1] = (m0.y != 0.f) ? 1.f : 0.f;
        w[2] = (m0.z != 0.f) ? 1.f : 0.f;  w[3] = (m0.w != 0.f) ? 1.f : 0.f;
        w[4] = (m1.x != 0.f) ? 1.f : 0.f;  w[5] = (m1.y != 0.f) ? 1.f : 0.f;
        w[6] = (m1.z != 0.f) ? 1.f : 0.f;  w[7] = (m1.w != 0.f) ? 1.f : 0.f;
    }

    float t[8] = {t0.x, t0.y, t0.z, t0.w, t1.x, t1.y, t1.z, t1.w};
    float n = 0.f, sm = 0.f, qq = 0.f;
    #pragma unroll
    for (int i = 0; i < 8; i++) {
        n  += w[i];
        sm += w[i] * t[i];
        qq += w[i] * t[i] * t[i];
    }

    // combine 4 quarters of a token (lanes q, q^1, q^2 within same token)
    n  += __shfl_xor_sync(0xFFFFFFFFu, n,  1);
    sm += __shfl_xor_sync(0xFFFFFFFFu, sm, 1);
    qq += __shfl_xor_sync(0xFFFFFFFFu, qq, 1);
    n  += __shfl_xor_sync(0xFFFFFFFFu, n,  2);
    sm += __shfl_xor_sync(0xFFFFFFFFu, sm, 2);
    qq += __shfl_xor_sync(0xFFFFFFFFu, qq, 2);

    __shared__ float acc[NG * 3];
    if (tid < NG * 3) acc[tid] = 0.f;
    __syncthreads();

    if (q == 0) {
        atomicAdd(&acc[grp * 3 + 0], n);
        atomicAdd(&acc[grp * 3 + 1], sm);
        atomicAdd(&acc[grp * 3 + 2], qq);
    }
    __syncthreads();

    if (tid < NG * 3)
        g_part[(size_t)(b * NC + c) * (NG * 3) + tid] = acc[tid];
}

__global__ __launch_bounds__(T2) void k2_finalize(
    const int* __restrict__ sample_id,
    const int* __restrict__ variate_id,
    float* __restrict__ out)
{
    const int b   = blockIdx.x >> 3;   // /SUB
    const int sub = blockIdx.x & (SUB - 1);
    const int tid = threadIdx.x;

    __shared__ float red[NG * 3];
    __shared__ float ls[NG][2];

    if (tid < NG * 3) {
        const float* p = g_part + (size_t)b * NC * (NG * 3) + tid;
        float a = 0.f;
        #pragma unroll 8
        for (int c = 0; c < NC; c++) a += p[(size_t)c * (NG * 3)];
        red[tid] = a;
    }
    __syncthreads();

    if (tid < NG) {
        float N  = red[tid * 3 + 0];
        float SM = red[tid * 3 + 1];
        float Q  = red[tid * 3 + 2];
        float dN  = (N == 0.f) ? 1.f : N;
        float loc = SM / dN;
        float vs  = fmaxf(Q - 2.f * loc * SM + loc * loc * N, 0.f);
        float dC  = N - 1.f;
        if (dC == 0.f) dC = 1.f;
        float scale = sqrtf(vs / dC + 1e-5f);
        if ((tid >> 2) == 0) { loc = 0.f; scale = 1.f; }   // sid==0 padding
        ls[tid][0] = loc;
        ls[tid][1] = scale;
    }
    __syncthreads();

    const int base = sub * (S_ / SUB);
    float* __restrict__ out_loc = out + (size_t)b * S_;
    float* __restrict__ out_sc  = out + (size_t)B_ * S_ + (size_t)b * S_;

    #pragma unroll 2
    for (int i = tid; i < S_ / SUB; i += T2) {
        const int s   = base + i;
        const int sid = __ldg(sample_id + b * S_ + s);
        const int v   = __ldg(variate_id + b * S_ + s);
        const int grp = sid * 4 + ((v < 4) ? 0 : (v - 3));
        out_loc[s] = ls[grp][0];
        out_sc[s]  = ls[grp][1];
    }
}

extern "C" void kernel_launch(void* const* d_in, const int* in_sizes, int n_in,
                              void* d_out, int out_size) {
    (void)in_sizes; (void)n_in; (void)out_size;
    const float* target     = (const float*)d_in[0];
    const void*  obs        = (const void*)d_in[1];
    const int*   sample_id  = (const int*)d_in[2];
    const int*   variate_id = (const int*)d_in[3];
    float*       out        = (float*)d_out;

    k1_partials<<<B_ * NC, T1>>>(target, obs, sample_id, variate_id);
    k2_finalize<<<B_ * SUB, T2>>>(sample_id, variate_id, out);
}

// round 6
// speedup vs baseline: 2.1007x; 1.0246x over previous
#include <cuda_runtime.h>

// OHLCVPackedScaler — single fused kernel.
// Phase 1: dense coalesced chunk scan -> per-(chunk,group) partial moments.
// Grid barrier (counter-based; all 256 CTAs co-resident).
// Phase 2: per-CTA L2 reduce of its batch's partials + loc/scale + scatter.

namespace {
constexpr int B_ = 4;
constexpr int S_ = 4096;
constexpr int D_ = 32;
constexpr int NG = 32;            // (sid 0..7) x (gid 0..3)
constexpr int NC = 64;            // chunks per batch
constexpr int CHUNK = S_ / NC;    // 64 tokens
constexpr int NT = 256;
constexpr int NCTA = B_ * NC;     // 256
}

__device__ float g_part[B_ * NC * NG * 3];   // [b][c][96]
__device__ unsigned int g_cnt0 = 0;          // barrier arrivals
__device__ unsigned int g_cnt1 = 0;          // exit arrivals (for reset)

__device__ __forceinline__ int detect_mode(const void* obs) {
    // 0 = bool bytes, 1 = int32 words, 2 = float32
    const unsigned int* w = reinterpret_cast<const unsigned int*>(obs);
    int mode = 1;
    #pragma unroll 8
    for (int i = 0; i < 64; i++) {
        unsigned int x = __ldg(w + i);
        if (x > 0x01010101u) { mode = 2; break; }
        if (x > 1u) mode = 0;
    }
    return mode;
}

__global__ __launch_bounds__(NT, 2) void ohlcv_fused(
    const float* __restrict__ target,
    const void* __restrict__ obs,
    const int* __restrict__ sample_id,
    const int* __restrict__ variate_id,
    float* __restrict__ out)
{
    const int b = blockIdx.x / NC;
    const int c = blockIdx.x - b * NC;
    const int tid   = threadIdx.x;
    const int tok_l = tid >> 2;          // 0..63
    const int q     = tid & 3;           // quarter: dims q*8..q*8+7
    const int s     = c * CHUNK + tok_l; // token within batch

    const int mode = detect_mode(obs);

    const int sid = __ldg(sample_id + b * S_ + s);
    const int v   = __ldg(variate_id + b * S_ + s);
    const int grp = sid * 4 + ((v < 4) ? 0 : (v - 3));

    // target quarter: 2x float4
    const float4* tp = reinterpret_cast<const float4*>(
        target + (size_t)(b * S_ + s) * D_) + q * 2;
    float4 t0 = __ldg(tp);
    float4 t1 = __ldg(tp + 1);

    // mask quarter -> 8 weights
    float w[8];
    const size_t eoff = (size_t)(b * S_ + s) * D_ + q * 8;   // element offset
    if (mode == 0) {
        uint2 m = __ldg(reinterpret_cast<const uint2*>((const unsigned char*)obs + eoff));
        w[0] = (m.x & 0x000000FFu) ? 1.f : 0.f;
        w[1] = (m.x & 0x0000FF00u) ? 1.f : 0.f;
        w[2] = (m.x & 0x00FF0000u) ? 1.f : 0.f;
        w[3] = (m.x & 0xFF000000u) ? 1.f : 0.f;
        w[4] = (m.y & 0x000000FFu) ? 1.f : 0.f;
        w[5] = (m.y & 0x0000FF00u) ? 1.f : 0.f;
        w[6] = (m.y & 0x00FF0000u) ? 1.f : 0.f;
        w[7] = (m.y & 0xFF000000u) ? 1.f : 0.f;
    } else if (mode == 1) {
        const uint4* mp = reinterpret_cast<const uint4*>((const unsigned int*)obs + eoff);
        uint4 m0 = __ldg(mp), m1 = __ldg(mp + 1);
        w[0] = m0.x ? 1.f : 0.f;  w[1] = m0.y ? 1.f : 0.f;
        w[2] = m0.z ? 1.f : 0.f;  w[3] = m0.w ? 1.f : 0.f;
        w[4] = m1.x ? 1.f : 0.f;  w[5] = m1.y ? 1.f : 0.f;
        w[6] = m1.z ? 1.f : 0.f;  w[7] = m1.w ? 1.f : 0.f;
    } else {
        const float4* mp = reinterpret_cast<const float4*>((const float*)obs + eoff);
        float4 m0 = __ldg(mp), m1 = __ldg(mp + 1);
        w[0] = (m0.x != 0.f) ? 1.f : 0.f;  w[1] = (m0.y != 0.f) ? 1.f : 0.f;
        w[2] = (m0.z != 0.f) ? 1.f : 0.f;  w[3] = (m0.w != 0.f) ? 1.f : 0.f;
        w[4] = (m1.x != 0.f) ? 1.f : 0.f;  w[5] = (m1.y != 0.f) ? 1.f : 0.f;
        w[6] = (m1.z != 0.f) ? 1.f : 0.f;  w[7] = (m1.w != 0.f) ? 1.f : 0.f;
    }

    float t[8] = {t0.x, t0.y, t0.z, t0.w, t1.x, t1.y, t1.z, t1.w};
    float n = 0.f, sm = 0.f, qq = 0.f;
    #pragma unroll
    for (int i = 0; i < 8; i++) {
        n  += w[i];
        sm += w[i] * t[i];
        qq += w[i] * t[i] * t[i];
    }

    // combine 4 quarters of a token (lanes within same token)
    n  += __shfl_xor_sync(0xFFFFFFFFu, n,  1);
    sm += __shfl_xor_sync(0xFFFFFFFFu, sm, 1);
    qq += __shfl_xor_sync(0xFFFFFFFFu, qq, 1);
    n  += __shfl_xor_sync(0xFFFFFFFFu, n,  2);
    sm += __shfl_xor_sync(0xFFFFFFFFu, sm, 2);
    qq += __shfl_xor_sync(0xFFFFFFFFu, qq, 2);

    __shared__ float acc[NG * 3];
    __shared__ int   sgrp[CHUNK];
    __shared__ float red[2][NG * 3];
    __shared__ float ls[NG][2];

    if (tid < NG * 3) acc[tid] = 0.f;
    __syncthreads();

    if (q == 0) {
        sgrp[tok_l] = grp;
        atomicAdd(&acc[grp * 3 + 0], n);
        atomicAdd(&acc[grp * 3 + 1], sm);
        atomicAdd(&acc[grp * 3 + 2], qq);
    }
    __syncthreads();

    if (tid < NG * 3)
        g_part[(size_t)(b * NC + c) * (NG * 3) + tid] = acc[tid];
    __threadfence();

    // ---- grid barrier (all NCTA CTAs resident: 256 CTAs / 148 SMs, occ>=2) ----
    if (tid == 0) {
        atomicAdd(&g_cnt0, 1u);
        while (atomicAdd(&g_cnt0, 0u) < (unsigned)NCTA) __nanosleep(40);
    }
    __syncthreads();
    __threadfence();

    // ---- per-CTA reduce of this batch's 64 chunk-partials (L2-hot, coalesced) ----
    {
        const int half = (tid < 96) ? 0 : 1;
        const int j    = (tid < 96) ? tid : tid - 96;
        if (tid < 192) {
            const float* p = g_part + (size_t)b * NC * (NG * 3)
                           + (size_t)half * 32 * (NG * 3) + j;
            float a = 0.f;
            #pragma unroll
            for (int cc = 0; cc < 32; cc++) a += p[(size_t)cc * (NG * 3)];
            red[half][j] = a;
        }
    }
    __syncthreads();

    if (tid < NG) {
        float N  = red[0][tid * 3 + 0] + red[1][tid * 3 + 0];
        float SM = red[0][tid * 3 + 1] + red[1][tid * 3 + 1];
        float Q  = red[0][tid * 3 + 2] + red[1][tid * 3 + 2];
        // uni2ts safe_div: denom==0 -> divide by 1
        float dN  = (N == 0.f) ? 1.f : N;
        float loc = SM / dN;
        float vs  = fmaxf(Q - 2.f * loc * SM + loc * loc * N, 0.f);
        float dC  = N - 1.f;
        if (dC == 0.f) dC = 1.f;
        float scale = sqrtf(vs / dC + 1e-5f);
        if ((tid >> 2) == 0) { loc = 0.f; scale = 1.f; }   // sid==0 padding
        ls[tid][0] = loc;
        ls[tid][1] = scale;
    }
    __syncthreads();

    // ---- scatter this CTA's chunk: 64 loc + 64 scale words, coalesced ----
    if (tid < 2 * CHUNK) {
        const int which = tid >> 6;          // 0 = loc, 1 = scale
        const int tt    = tid & (CHUNK - 1);
        const int ss    = c * CHUNK + tt;
        const float val = ls[sgrp[tt]][which];
        float* dst = which ? (out + (size_t)B_ * S_ + (size_t)b * S_ + ss)
                           : (out + (size_t)b * S_ + ss);
        *dst = val;
    }

    // ---- reset counters for graph-replay safety ----
    if (tid == 0) {
        unsigned r = atomicAdd(&g_cnt1, 1u);
        if (r == (unsigned)(NCTA - 1)) {
            atomicExch(&g_cnt0, 0u);
            atomicExch(&g_cnt1, 0u);
        }
    }
}

extern "C" void kernel_launch(void* const* d_in, const int* in_sizes, int n_in,
                              void* d_out, int out_size) {
    (void)in_sizes; (void)n_in; (void)out_size;
    const float* target     = (const float*)d_in[0];
    const void*  obs        = (const void*)d_in[1];
    const int*   sample_id  = (const int*)d_in[2];
    const int*   variate_id = (const int*)d_in[3];
    float*       out        = (float*)d_out;
    ohlcv_fused<<<NCTA, NT>>>(target, obs, sample_id, variate_id, out);
}

// round 7
// speedup vs baseline: 2.1375x; 1.0175x over previous
#include <cuda_runtime.h>

// OHLCVPackedScaler — single fused kernel, one-wave grid (128 CTAs).
// Phase 1: dense coalesced chunk scan -> per-(chunk,group) partial moments.
// Grid barrier (single arrival RMW + volatile-load poll).
// Phase 2: per-CTA L2 reduce of its batch's partials + loc/scale + scatter.

namespace {
constexpr int B_ = 4;
constexpr int S_ = 4096;
constexpr int D_ = 32;
constexpr int NG = 32;            // (sid 0..7) x (gid 0..3)
constexpr int NC = 32;            // chunks per batch
constexpr int CHUNK = S_ / NC;    // 128 tokens
constexpr int NT = 512;
constexpr int NCTA = B_ * NC;     // 128 (<= 148 SMs -> single wave)
}

__device__ float g_part[B_ * NC * NG * 3];   // [b][c][96]
__device__ unsigned int g_cnt0 = 0;          // barrier arrivals
__device__ unsigned int g_cnt1 = 0;          // exit arrivals (reset for replay)

__device__ __forceinline__ int detect_mode(const void* obs) {
    // 0 = bool bytes, 1 = int32 words, 2 = float32
    const unsigned int* w = reinterpret_cast<const unsigned int*>(obs);
    int mode = 1;
    #pragma unroll 8
    for (int i = 0; i < 64; i++) {
        unsigned int x = __ldg(w + i);
        if (x > 0x01010101u) { mode = 2; break; }
        if (x > 1u) mode = 0;
    }
    return mode;
}

__global__ __launch_bounds__(NT, 1) void ohlcv_fused(
    const float* __restrict__ target,
    const void* __restrict__ obs,
    const int* __restrict__ sample_id,
    const int* __restrict__ variate_id,
    float* __restrict__ out)
{
    const int b = blockIdx.x / NC;
    const int c = blockIdx.x - b * NC;
    const int tid   = threadIdx.x;
    const int tok_l = tid >> 2;          // 0..127
    const int q     = tid & 3;           // quarter: dims q*8..q*8+7
    const int s     = c * CHUNK + tok_l; // token within batch

    const int mode = detect_mode(obs);

    const int sid = __ldg(sample_id + b * S_ + s);
    const int v   = __ldg(variate_id + b * S_ + s);
    const int grp = sid * 4 + ((v < 4) ? 0 : (v - 3));

    // target quarter: 2x float4 (warp covers 1KB contiguous per instruction pair)
    const float4* tp = reinterpret_cast<const float4*>(
        target + (size_t)(b * S_ + s) * D_) + q * 2;
    float4 t0 = __ldg(tp);
    float4 t1 = __ldg(tp + 1);

    // mask quarter -> 8 weights
    float w[8];
    const size_t eoff = (size_t)(b * S_ + s) * D_ + q * 8;   // element offset
    if (mode == 0) {
        uint2 m = __ldg(reinterpret_cast<const uint2*>((const unsigned char*)obs + eoff));
        w[0] = (m.x & 0x000000FFu) ? 1.f : 0.f;
        w[1] = (m.x & 0x0000FF00u) ? 1.f : 0.f;
        w[2] = (m.x & 0x00FF0000u) ? 1.f : 0.f;
        w[3] = (m.x & 0xFF000000u) ? 1.f : 0.f;
        w[4] = (m.y & 0x000000FFu) ? 1.f : 0.f;
        w[5] = (m.y & 0x0000FF00u) ? 1.f : 0.f;
        w[6] = (m.y & 0x00FF0000u) ? 1.f : 0.f;
        w[7] = (m.y & 0xFF000000u) ? 1.f : 0.f;
    } else if (mode == 1) {
        const uint4* mp = reinterpret_cast<const uint4*>((const unsigned int*)obs + eoff);
        uint4 m0 = __ldg(mp), m1 = __ldg(mp + 1);
        w[0] = m0.x ? 1.f : 0.f;  w[1] = m0.y ? 1.f : 0.f;
        w[2] = m0.z ? 1.f : 0.f;  w[3] = m0.w ? 1.f : 0.f;
        w[4] = m1.x ? 1.f : 0.f;  w[5] = m1.y ? 1.f : 0.f;
        w[6] = m1.z ? 1.f : 0.f;  w[7] = m1.w ? 1.f : 0.f;
    } else {
        const float4* mp = reinterpret_cast<const float4*>((const float*)obs + eoff);
        float4 m0 = __ldg(mp), m1 = __ldg(mp + 1);
        w[0] = (m0.x != 0.f) ? 1.f : 0.f;  w[1] = (m0.y != 0.f) ? 1.f : 0.f;
        w[2] = (m0.z != 0.f) ? 1.f : 0.f;  w[3] = (m0.w != 0.f) ? 1.f : 0.f;
        w[4] = (m1.x != 0.f) ? 1.f : 0.f;  w[5] = (m1.y != 0.f) ? 1.f : 0.f;
        w[6] = (m1.z != 0.f) ? 1.f : 0.f;  w[7] = (m1.w != 0.f) ? 1.f : 0.f;
    }

    float t[8] = {t0.x, t0.y, t0.z, t0.w, t1.x, t1.y, t1.z, t1.w};
    float n = 0.f, sm = 0.f, qq = 0.f;
    #pragma unroll
    for (int i = 0; i < 8; i++) {
        n  += w[i];
        sm += w[i] * t[i];
        qq += w[i] * t[i] * t[i];
    }

    // combine 4 quarters of a token (lanes within same token)
    n  += __shfl_xor_sync(0xFFFFFFFFu, n,  1);
    sm += __shfl_xor_sync(0xFFFFFFFFu, sm, 1);
    qq += __shfl_xor_sync(0xFFFFFFFFu, qq, 1);
    n  += __shfl_xor_sync(0xFFFFFFFFu, n,  2);
    sm += __shfl_xor_sync(0xFFFFFFFFu, sm, 2);
    qq += __shfl_xor_sync(0xFFFFFFFFu, qq, 2);

    __shared__ float acc[NG * 3];
    __shared__ int   sgrp[CHUNK];
    __shared__ float red[2][NG * 3];
    __shared__ float ls[NG][2];

    if (tid < NG * 3) acc[tid] = 0.f;
    __syncthreads();

    if (q == 0) {
        sgrp[tok_l] = grp;
        atomicAdd(&acc[grp * 3 + 0], n);
        atomicAdd(&acc[grp * 3 + 1], sm);
        atomicAdd(&acc[grp * 3 + 2], qq);
    }
    __syncthreads();

    if (tid < NG * 3)
        g_part[(size_t)(b * NC + c) * (NG * 3) + tid] = acc[tid];
    __threadfence();
    __syncthreads();

    // ---- grid barrier: single wave (128 CTAs), RMW arrival + volatile poll ----
    if (tid == 0) {
        atomicAdd(&g_cnt0, 1u);
        volatile unsigned int* pc = &g_cnt0;
        while (*pc < (unsigned)NCTA) __nanosleep(32);
    }
    __syncthreads();
    __threadfence();

    // ---- per-CTA reduce of this batch's 32 chunk-partials (L2-hot) ----
    if (tid < 192) {
        const int half = tid / 96;           // 0/1 -> chunks [0,16) / [16,32)
        const int j    = tid - half * 96;
        const float* p = g_part + (size_t)b * NC * (NG * 3)
                       + (size_t)half * 16 * (NG * 3) + j;
        float a = 0.f;
        #pragma unroll
        for (int cc = 0; cc < 16; cc++) a += p[(size_t)cc * (NG * 3)];
        red[half][j] = a;
    }
    __syncthreads();

    if (tid < NG) {
        float N  = red[0][tid * 3 + 0] + red[1][tid * 3 + 0];
        float SM = red[0][tid * 3 + 1] + red[1][tid * 3 + 1];
        float Q  = red[0][tid * 3 + 2] + red[1][tid * 3 + 2];
        // uni2ts safe_div: denom==0 -> divide by 1
        float dN  = (N == 0.f) ? 1.f : N;
        float loc = SM / dN;
        float vs  = fmaxf(Q - 2.f * loc * SM + loc * loc * N, 0.f);
        float dC  = N - 1.f;
        if (dC == 0.f) dC = 1.f;
        float scale = sqrtf(vs / dC + 1e-5f);
        if ((tid >> 2) == 0) { loc = 0.f; scale = 1.f; }   // sid==0 padding
        ls[tid][0] = loc;
        ls[tid][1] = scale;
    }
    __syncthreads();

    // ---- scatter this CTA's chunk: 128 loc + 128 scale words, coalesced ----
    if (tid < 2 * CHUNK) {
        const int which = tid >> 7;              // 0 = loc, 1 = scale
        const int tt    = tid & (CHUNK - 1);
        const int ss    = c * CHUNK + tt;
        const float val = ls[sgrp[tt]][which];
        float* dst = which ? (out + (size_t)B_ * S_ + (size_t)b * S_ + ss)
                           : (out + (size_t)b * S_ + ss);
        *dst = val;
    }

    // ---- reset counters for graph-replay safety ----
    if (tid == 0) {
        unsigned r = atomicAdd(&g_cnt1, 1u);
        if (r == (unsigned)(NCTA - 1)) {
            atomicExch(&g_cnt0, 0u);
            atomicExch(&g_cnt1, 0u);
        }
    }
}

extern "C" void kernel_launch(void* const* d_in, const int* in_sizes, int n_in,
                              void* d_out, int out_size) {
    (void)in_sizes; (void)n_in; (void)out_size;
    const float* target     = (const float*)d_in[0];
    const void*  obs        = (const void*)d_in[1];
    const int*   sample_id  = (const int*)d_in[2];
    const int*   variate_id = (const int*)d_in[3];
    float*       out        = (float*)d_out;
    ohlcv_fused<<<NCTA, NT>>>(target, obs, sample_id, variate_id, out);
}

// round 8
// speedup vs baseline: 2.5221x; 1.1799x over previous
#include <cuda_runtime.h>

// OHLCVPackedScaler — single fused kernel, one-wave grid (128 CTAs),
// per-batch grid barrier, warp-local ballot mask-dtype detection,
// speculative dual-interpretation mask loads.

namespace {
constexpr int B_ = 4;
constexpr int S_ = 4096;
constexpr int D_ = 32;
constexpr int NG = 32;            // (sid 0..7) x (gid 0..3)
constexpr int NC = 32;            // chunks per batch
constexpr int CHUNK = S_ / NC;    // 128 tokens
constexpr int NT = 512;
constexpr int NCTA = B_ * NC;     // 128 (single wave)
constexpr int PAD = 64;           // counter padding (256B) to split L2 lines
}

__device__ float g_part[B_ * NC * NG * 3];   // [b][c][96]
__device__ unsigned int g_bar[B_ * PAD];     // per-batch barrier arrivals
__device__ unsigned int g_fin[B_ * PAD];     // per-batch exit arrivals (reset)

__global__ __launch_bounds__(NT, 1) void ohlcv_fused(
    const float* __restrict__ target,
    const void* __restrict__ obs,
    const int* __restrict__ sample_id,
    const int* __restrict__ variate_id,
    float* __restrict__ out)
{
    const int b = blockIdx.x / NC;
    const int c = blockIdx.x - b * NC;
    const int tid   = threadIdx.x;
    const int lane  = tid & 31;
    const int tok_l = tid >> 2;          // 0..127
    const int q     = tid & 3;           // quarter: dims q*8..q*8+7
    const int s     = c * CHUNK + tok_l; // token within batch

    // ---- issue ALL global loads up front (MLP ~7) ----
    const int sid = __ldg(sample_id + b * S_ + s);
    const int v   = __ldg(variate_id + b * S_ + s);

    const float4* tp = reinterpret_cast<const float4*>(
        target + (size_t)(b * S_ + s) * D_) + q * 2;
    float4 t0 = __ldg(tp);
    float4 t1 = __ldg(tp + 1);

    const size_t eoff = (size_t)(b * S_ + s) * D_ + q * 8;   // element offset
    // byte interpretation (bool mask)
    uint2 mb = __ldg(reinterpret_cast<const uint2*>(
                     (const unsigned char*)obs + eoff));
    // word interpretation (int32 OR float32 mask: both are "bits != 0")
    const uint4* mwp = reinterpret_cast<const uint4*>(
                       (const unsigned int*)obs + eoff);
    uint4 mw0 = __ldg(mwp);
    uint4 mw1 = __ldg(mwp + 1);

    // ---- warp-local mask dtype detection from first 256B (L1 broadcast) ----
    // bool-bytes iff some word in (1, 0x01010101] and none above 0x01010101.
    bool big = false, nb = false;
    {
        uint4 x = __ldg(reinterpret_cast<const uint4*>(obs) + (lane & 15));
        unsigned mx = max(max(x.x, x.y), max(x.z, x.w));
        big = mx > 0x01010101u;
        nb  = mx > 1u;
    }
    const unsigned any_big = __ballot_sync(0xFFFFFFFFu, big);
    const unsigned any_nb  = __ballot_sync(0xFFFFFFFFu, nb);
    const bool is_bytes = (any_big == 0u) && (any_nb != 0u);

    // ---- weights ----
    float w[8];
    if (is_bytes) {
        w[0] = (mb.x & 0x000000FFu) ? 1.f : 0.f;
        w[1] = (mb.x & 0x0000FF00u) ? 1.f : 0.f;
        w[2] = (mb.x & 0x00FF0000u) ? 1.f : 0.f;
        w[3] = (mb.x & 0xFF000000u) ? 1.f : 0.f;
        w[4] = (mb.y & 0x000000FFu) ? 1.f : 0.f;
        w[5] = (mb.y & 0x0000FF00u) ? 1.f : 0.f;
        w[6] = (mb.y & 0x00FF0000u) ? 1.f : 0.f;
        w[7] = (mb.y & 0xFF000000u) ? 1.f : 0.f;
    } else {
        w[0] = mw0.x ? 1.f : 0.f;  w[1] = mw0.y ? 1.f : 0.f;
        w[2] = mw0.z ? 1.f : 0.f;  w[3] = mw0.w ? 1.f : 0.f;
        w[4] = mw1.x ? 1.f : 0.f;  w[5] = mw1.y ? 1.f : 0.f;
        w[6] = mw1.z ? 1.f : 0.f;  w[7] = mw1.w ? 1.f : 0.f;
    }

    const int grp = sid * 4 + ((v < 4) ? 0 : (v - 3));

    float t[8] = {t0.x, t0.y, t0.z, t0.w, t1.x, t1.y, t1.z, t1.w};
    float n = 0.f, sm = 0.f, qq = 0.f;
    #pragma unroll
    for (int i = 0; i < 8; i++) {
        n  += w[i];
        sm += w[i] * t[i];
        qq += w[i] * t[i] * t[i];
    }

    // combine 4 quarters of a token
    n  += __shfl_xor_sync(0xFFFFFFFFu, n,  1);
    sm += __shfl_xor_sync(0xFFFFFFFFu, sm, 1);
    qq += __shfl_xor_sync(0xFFFFFFFFu, qq, 1);
    n  += __shfl_xor_sync(0xFFFFFFFFu, n,  2);
    sm += __shfl_xor_sync(0xFFFFFFFFu, sm, 2);
    qq += __shfl_xor_sync(0xFFFFFFFFu, qq, 2);

    __shared__ float acc[NG * 3];
    __shared__ int   sgrp[CHUNK];
    __shared__ float red[2][NG * 3];
    __shared__ float ls[NG][2];

    if (tid < NG * 3) acc[tid] = 0.f;
    __syncthreads();

    if (q == 0) {
        sgrp[tok_l] = grp;
        atomicAdd(&acc[grp * 3 + 0], n);
        atomicAdd(&acc[grp * 3 + 1], sm);
        atomicAdd(&acc[grp * 3 + 2], qq);
    }
    __syncthreads();

    if (tid < NG * 3)
        g_part[(size_t)(b * NC + c) * (NG * 3) + tid] = acc[tid];
    __threadfence();
    __syncthreads();

    // ---- per-batch barrier: 32 arrivals, volatile poll ----
    if (tid == 0) {
        atomicAdd(&g_bar[b * PAD], 1u);
        volatile unsigned int* pc = &g_bar[b * PAD];
        while (*pc < (unsigned)NC) __nanosleep(32);
    }
    __syncthreads();
    __threadfence();

    // ---- per-CTA reduce of this batch's 32 chunk-partials (L2-hot) ----
    if (tid < 192) {
        const int half = tid / 96;           // chunks [0,16) / [16,32)
        const int j    = tid - half * 96;
        const float* p = g_part + (size_t)b * NC * (NG * 3)
                       + (size_t)half * 16 * (NG * 3) + j;
        float a = 0.f;
        #pragma unroll
        for (int cc = 0; cc < 16; cc++) a += p[(size_t)cc * (NG * 3)];
        red[half][j] = a;
    }
    __syncthreads();

    if (tid < NG) {
        float N  = red[0][tid * 3 + 0] + red[1][tid * 3 + 0];
        float SM = red[0][tid * 3 + 1] + red[1][tid * 3 + 1];
        float Q  = red[0][tid * 3 + 2] + red[1][tid * 3 + 2];
        // uni2ts safe_div: denom==0 -> divide by 1
        float dN  = (N == 0.f) ? 1.f : N;
        float loc = SM / dN;
        float vs  = fmaxf(Q - 2.f * loc * SM + loc * loc * N, 0.f);
        float dC  = N - 1.f;
        if (dC == 0.f) dC = 1.f;
        float scale = sqrtf(vs / dC + 1e-5f);
        if ((tid >> 2) == 0) { loc = 0.f; scale = 1.f; }   // sid==0 padding
        ls[tid][0] = loc;
        ls[tid][1] = scale;
    }
    __syncthreads();

    // ---- scatter this CTA's chunk: 128 loc + 128 scale words, coalesced ----
    if (tid < 2 * CHUNK) {
        const int which = tid >> 7;              // 0 = loc, 1 = scale
        const int tt    = tid & (CHUNK - 1);
        const int ss    = c * CHUNK + tt;
        const float val = ls[sgrp[tt]][which];
        float* dst = which ? (out + (size_t)B_ * S_ + (size_t)b * S_ + ss)
                           : (out + (size_t)b * S_ + ss);
        *dst = val;
    }

    // ---- per-batch reset for graph-replay safety ----
    // A CTA arrives at g_fin only after its barrier poll completed, so when
    // the 32nd arrives every poll in this batch is done -> safe to reset.
    if (tid == 0) {
        unsigned r = atomicAdd(&g_fin[b * PAD], 1u);
        if (r == (unsigned)(NC - 1)) {
            atomicExch(&g_bar[b * PAD], 0u);
            atomicExch(&g_fin[b * PAD], 0u);
        }
    }
}

extern "C" void kernel_launch(void* const* d_in, const int* in_sizes, int n_in,
                              void* d_out, int out_size) {
    (void)in_sizes; (void)n_in; (void)out_size;
    const float* target     = (const float*)d_in[0];
    const void*  obs        = (const void*)d_in[1];
    const int*   sample_id  = (const int*)d_in[2];
    const int*   variate_id = (const int*)d_in[3];
    float*       out        = (float*)d_out;
    ohlcv_fused<<<NCTA, NT>>>(target, obs, sample_id, variate_id, out);
}